// round 4
// baseline (speedup 1.0000x reference)
#include <cuda_runtime.h>
#include <cooperative_groups.h>

namespace cg = cooperative_groups;

#define N_QUBITS 15
#define N_LAYERS 4
#define BATCHN   64
#define NSTATE   (1 << N_QUBITS)   // 32768
#define NTHREADS 1024

// 16 MB L2-resident state scratch: [batch][32768] complex64 as float2.
__device__ float2 g_state[BATCHN * NSTATE];

__device__ __forceinline__ void crot(float2& a0, float2& a1,
                                     float2 u0, float2 u1, float2 u2, float2 u3) {
  float2 r0, r1;
  r0.x = u0.x * a0.x - u0.y * a0.y + u1.x * a1.x - u1.y * a1.y;
  r0.y = u0.x * a0.y + u0.y * a0.x + u1.x * a1.y + u1.y * a1.x;
  r1.x = u2.x * a0.x - u2.y * a0.y + u3.x * a1.x - u3.y * a1.y;
  r1.y = u2.x * a0.y + u2.y * a0.x + u3.x * a1.y + u3.y * a1.x;
  a0 = r0; a1 = r1;
}

// Rotation on register-local bit BIT of a 16-amp subcube.
template<int BIT>
__device__ __forceinline__ void rotg16(float2* a, const float2* su) {
  float2 u0 = su[0], u1 = su[1], u2 = su[2], u3 = su[3];
#pragma unroll
  for (int j = 0; j < 16; j++) {
    if (((j >> BIT) & 1) == 0) {
      crot(a[j], a[j | (1 << BIT)], u0, u1, u2, u3);
    }
  }
}

// CNOT with control BC / target BT both in register bits.
template<int BC, int BT>
__device__ __forceinline__ void cnotl16(float2* a) {
#pragma unroll
  for (int j = 0; j < 16; j++) {
    if (((j >> BC) & 1) == 1 && ((j >> BT) & 1) == 0) {
      int k = j | (1 << BT);
      float2 t = a[j]; a[j] = a[k]; a[k] = t;
    }
  }
}

// X on register bit BT conditioned on a runtime control bit.
template<int BT>
__device__ __forceinline__ void xcond16(float2* a, bool c) {
#pragma unroll
  for (int j = 0; j < 16; j++) {
    if (((j >> BT) & 1) == 0) {
      int k = j | (1 << BT);
      float2 t0 = a[j], t1 = a[k];
      a[j] = c ? t1 : t0;
      a[k] = c ? t0 : t1;
    }
  }
}

// Rotation on the lane-bit qubit (amp bit == lane0). Pair partner = lane^1.
__device__ __forceinline__ void rot_lane(float2* a, const float2* su, int lane0) {
  float2 u0 = su[0], u1 = su[1], u2 = su[2], u3 = su[3];
  float2 ua = lane0 ? u3 : u0;  // coefficient on own amp
  float2 ub = lane0 ? u2 : u1;  // coefficient on partner amp
#pragma unroll
  for (int j = 0; j < 16; j++) {
    float px = __shfl_xor_sync(0xffffffffu, a[j].x, 1);
    float py = __shfl_xor_sync(0xffffffffu, a[j].y, 1);
    float2 o = a[j];
    a[j].x = ua.x * o.x - ua.y * o.y + ub.x * px - ub.y * py;
    a[j].y = ua.x * o.y + ua.y * o.x + ub.x * py + ub.y * px;
  }
}

// CNOT: control = register bit0, target = lane-bit qubit -> lane swap for odd j.
__device__ __forceinline__ void cnot_reg_to_lane(float2* a) {
#pragma unroll
  for (int j = 1; j < 16; j += 2) {
    a[j].x = __shfl_xor_sync(0xffffffffu, a[j].x, 1);
    a[j].y = __shfl_xor_sync(0xffffffffu, a[j].y, 1);
  }
}

// Amp index convention: qubit q <-> bit (14 - q). Class = amp bits 14..13.
__global__ void __launch_bounds__(NTHREADS, 1) __cluster_dims__(2, 1, 1)
qdarts_kernel(const float* __restrict__ x, const float* __restrict__ Pm,
              const float* __restrict__ Qm, const float* __restrict__ rotp,
              const float* __restrict__ gum, float* __restrict__ out)
{
  __shared__ float2 sU[N_LAYERS * N_QUBITS * 4];
  __shared__ float  sw[N_QUBITS][2];
  __shared__ float  sred[4];

  cg::cluster_group cluster = cg::this_cluster();
  const int tid   = threadIdx.x;
  const int b     = blockIdx.x >> 1;
  const int rank  = blockIdx.x & 1;            // cluster rank
  const int lane0 = tid & 1;                   // lane-bit qubit value
  const int s     = (rank << 9) | (tid >> 1);  // 10-bit "rest" index

  // ---- Gate selection: argmax(P@Q + gumbel); build RX/RY/RZ(theta). ----
  if (tid < N_LAYERS * N_QUBITS) {
    const int idx = tid;
    float best = -1e30f; int gb = 0;
#pragma unroll
    for (int gg = 0; gg < 3; gg++) {
      float logit = 0.f;
#pragma unroll
      for (int k = 0; k < 4; k++)
        logit += Pm[idx * 4 + k] * Qm[(idx * 4 + k) * 3 + gg];
      float v = logit + gum[idx * 3 + gg];
      if (v > best) { best = v; gb = gg; }
    }
    float th = rotp[idx];
    float sv, cv;
    sincosf(0.5f * th, &sv, &cv);
    float2 u0, u1, u2, u3;
    if (gb == 0) {        // RX
      u0 = make_float2(cv, 0.f);   u1 = make_float2(0.f, -sv);
      u2 = make_float2(0.f, -sv);  u3 = make_float2(cv, 0.f);
    } else if (gb == 1) { // RY
      u0 = make_float2(cv, 0.f);   u1 = make_float2(-sv, 0.f);
      u2 = make_float2(sv, 0.f);   u3 = make_float2(cv, 0.f);
    } else {              // RZ
      u0 = make_float2(cv, -sv);   u1 = make_float2(0.f, 0.f);
      u2 = make_float2(0.f, 0.f);  u3 = make_float2(cv, sv);
    }
    sU[idx * 4 + 0] = u0; sU[idx * 4 + 1] = u1;
    sU[idx * 4 + 2] = u2; sU[idx * 4 + 3] = u3;
  }
  if (tid < N_QUBITS) {
    float xv = x[b * N_QUBITS + tid];
    float sv, cv;
    sincosf(0.5f * xv, &sv, &cv);
    sw[tid][0] = cv; sw[tid][1] = sv;
  }
  if (tid < 4) sred[tid] = 0.f;
  __syncthreads();

  float2* S = g_state + b * NSTATE;
  float ps0 = 0.f, ps1 = 0.f, ps2 = 0.f, ps3 = 0.f;

#pragma unroll 1
  for (int l = 0; l < N_LAYERS; l++) {
    const float2* UL = &sU[l * N_QUBITS * 4];

    // ---- Pass A: amp = (j<<11)|(lane0<<10)|s. j bits 3..0 = q0..q3, lane = q4 ----
    {
      float2 a[16];
      if (l == 0) {
        float pref = sw[4][lane0];
#pragma unroll
        for (int q = 5; q < 15; q++) pref *= sw[q][(s >> (14 - q)) & 1];
#pragma unroll
        for (int j = 0; j < 16; j++) {
          float v = pref;
#pragma unroll
          for (int q = 0; q < 4; q++) v *= sw[q][(j >> (3 - q)) & 1];
          a[j] = make_float2(v, 0.f);
        }
      } else {
#pragma unroll
        for (int j = 0; j < 16; j++) a[j] = S[(j << 11) | (lane0 << 10) | s];
        xcond16<3>(a, (s & 1) != 0);  // deferred CNOT(14,0) of layer l-1
      }
      rotg16<3>(a, UL + 0 * 4);   // R_q0
      rotg16<2>(a, UL + 1 * 4);   // R_q1
      rotg16<1>(a, UL + 2 * 4);   // R_q2
      rotg16<0>(a, UL + 3 * 4);   // R_q3
      rot_lane(a, UL + 4 * 4, lane0);  // R_q4
      cnotl16<3, 2>(a);           // CNOT(0,1)
      cnotl16<2, 1>(a);           // CNOT(1,2)
      cnotl16<1, 0>(a);           // CNOT(2,3)
      cnot_reg_to_lane(a);        // CNOT(3,4)
#pragma unroll
      for (int j = 0; j < 16; j++) S[(j << 11) | (lane0 << 10) | s] = a[j];
    }
    cluster.sync();

    // ---- Pass B: amp = (hi5<<10)|(j<<6)|(lane0<<5)|lo5. j = q5..q8, lane = q9 ----
    {
      const int hi5 = s >> 5, lo5 = s & 31;
      const int base = (hi5 << 10) | (lane0 << 5) | lo5;
      float2 a[16];
#pragma unroll
      for (int j = 0; j < 16; j++) a[j] = S[base | (j << 6)];
      rotg16<3>(a, UL + 5 * 4);   // R_q5
      rotg16<2>(a, UL + 6 * 4);   // R_q6
      rotg16<1>(a, UL + 7 * 4);   // R_q7
      rotg16<0>(a, UL + 8 * 4);   // R_q8
      rot_lane(a, UL + 9 * 4, lane0);  // R_q9
      xcond16<3>(a, (hi5 & 1) != 0);   // CNOT(4,5): control amp bit10
      cnotl16<3, 2>(a);           // CNOT(5,6)
      cnotl16<2, 1>(a);           // CNOT(6,7)
      cnotl16<1, 0>(a);           // CNOT(7,8)
      cnot_reg_to_lane(a);        // CNOT(8,9)
#pragma unroll
      for (int j = 0; j < 16; j++) S[base | (j << 6)] = a[j];
    }
    cluster.sync();

    // ---- Pass C: amp = (s<<5)|(j<<1)|lane0. j = q10..q13, lane = q14 ----
    {
      const int base = (s << 5) | lane0;
      float2 a[16];
#pragma unroll
      for (int j = 0; j < 16; j++) a[j] = S[base | (j << 1)];
      rotg16<3>(a, UL + 10 * 4);  // R_q10
      rotg16<2>(a, UL + 11 * 4);  // R_q11
      rotg16<1>(a, UL + 12 * 4);  // R_q12
      rotg16<0>(a, UL + 13 * 4);  // R_q13
      rot_lane(a, UL + 14 * 4, lane0);  // R_q14
      xcond16<3>(a, (s & 1) != 0);      // CNOT(9,10): control amp bit5
      cnotl16<3, 2>(a);           // CNOT(10,11)
      cnotl16<2, 1>(a);           // CNOT(11,12)
      cnotl16<1, 0>(a);           // CNOT(12,13)
      cnot_reg_to_lane(a);        // CNOT(13,14)

      if (l < N_LAYERS - 1) {
#pragma unroll
        for (int j = 0; j < 16; j++) S[base | (j << 1)] = a[j];
      } else {
        // Last layer: fold CNOT(14,0) + |amp|^2 class reduction.
        // class = amp bits 14..13 = s bits 9..8; CNOT(14,0) control = amp
        // bit0 = lane0 flips class MSB.
        float p = 0.f;
#pragma unroll
        for (int j = 0; j < 16; j++)
          p += a[j].x * a[j].x + a[j].y * a[j].y;
        int c = (s >> 8) & 3;
        if (lane0) c ^= 2;
        if      (c == 0) ps0 = p;
        else if (c == 1) ps1 = p;
        else if (c == 2) ps2 = p;
        else             ps3 = p;
      }
    }
    if (l < N_LAYERS - 1) cluster.sync();
  }

  // ---- Reduce class sums: warp -> CTA shared -> cross-CTA (DSMEM) ----
#pragma unroll
  for (int o = 16; o > 0; o >>= 1) {
    ps0 += __shfl_xor_sync(0xffffffffu, ps0, o);
    ps1 += __shfl_xor_sync(0xffffffffu, ps1, o);
    ps2 += __shfl_xor_sync(0xffffffffu, ps2, o);
    ps3 += __shfl_xor_sync(0xffffffffu, ps3, o);
  }
  if ((tid & 31) == 0) {
    atomicAdd(&sred[0], ps0);
    atomicAdd(&sred[1], ps1);
    atomicAdd(&sred[2], ps2);
    atomicAdd(&sred[3], ps3);
  }
  __syncthreads();

  if (rank == 1 && tid < 4) {
    float* dst = cluster.map_shared_rank(sred, 0);
    atomicAdd(dst + tid, sred[tid]);
  }
  cluster.sync();
  if (rank == 0 && tid < 4) out[b * 4 + tid] = sred[tid];
}

extern "C" void kernel_launch(void* const* d_in, const int* in_sizes, int n_in,
                              void* d_out, int out_size) {
  const float* x    = (const float*)d_in[0];
  const float* P    = (const float*)d_in[1];
  const float* Q    = (const float*)d_in[2];
  const float* rotp = (const float*)d_in[3];
  const float* gum  = (const float*)d_in[4];
  qdarts_kernel<<<BATCHN * 2, NTHREADS>>>(x, P, Q, rotp, gum, (float*)d_out);
}